// round 16
// baseline (speedup 1.0000x reference)
#include <cuda_runtime.h>
#include <cuda_fp16.h>
#include <math.h>
#include <stdint.h>

#define BATCH 64
#define DMODEL 128
#define NN 2048
#define HEAD 4
#define DK 32
#define NT 128
#define NTILES (NN/NT)  // 16

#define IMG_SZ 34816       // 128 rows * 272 B
#define ROWB 272
// k_qv: A | B | D fp32 | biases | Q(img staging)
#define QV_A 0
#define QV_B 34816
#define QV_D 69632         // fp32 [128][129]
#define QV_SB 135680
#define QV_Q 136704
#define SMEM_QV 171520
// k_out (2 tiles): Mb | Cs | q0 | v0 | q1 | v1
#define KO_A 0
#define KO_C 34816
#define KO_BQ0 69632
#define KO_BV0 104448
#define KO_BQ1 139264
#define KO_BV1 174080
#define SMEM_OUT 208896
// k_prolog dyn smem (biasdyn partition)
#define PL_P 0             // 65536 : p[8][2048]
#define PL_RED 65536       // 1024
#define PL_A1 66560        // 320
#define PL_INV 66880       // 32
#define SMEM_PL 66944

// ---------------- device globals ----------------
static __device__ float g_keysm[HEAD * NN * DK];
static __device__ float g_biasdyn[NN * DK];
static __device__ float g_kv[BATCH * HEAD * DK * DK];
static __device__ float g_bias2[DMODEL * NN];
static __device__ float g_Cp[DMODEL * DK];
static __device__ __align__(16) unsigned char g_wimg[3 * 32768];                      // Wq, Wv, Cs
static __device__ __align__(16) unsigned char g_qimg[(size_t)BATCH * NTILES * 32768];
static __device__ __align__(16) unsigned char g_vimg[(size_t)BATCH * NTILES * 32768];
static __device__ __align__(16) unsigned char g_Mb[(size_t)BATCH * 32768];

// ---------------- helpers ----------------
__device__ __forceinline__ uint32_t smem_u32(const void* p) {
    uint32_t a;
    asm("{ .reg .u64 t; cvta.to.shared.u64 t, %1; cvt.u32.u64 %0, t; }" : "=r"(a) : "l"(p));
    return a;
}
__device__ __forceinline__ unsigned short hf1(float v) {
    return __half_as_ushort(__float2half_rn(v));
}
__device__ __forceinline__ uint4 pack8(const unsigned short* h) {
    uint4 u;
    u.x = (uint32_t)h[0] | ((uint32_t)h[1] << 16);
    u.y = (uint32_t)h[2] | ((uint32_t)h[3] << 16);
    u.z = (uint32_t)h[4] | ((uint32_t)h[5] << 16);
    u.w = (uint32_t)h[6] | ((uint32_t)h[7] << 16);
    return u;
}
__device__ __forceinline__ float warp_max(float v) {
    #pragma unroll
    for (int o = 16; o; o >>= 1) v = fmaxf(v, __shfl_xor_sync(0xffffffffu, v, o));
    return v;
}
__device__ __forceinline__ float warp_sum(float v) {
    #pragma unroll
    for (int o = 16; o; o >>= 1) v += __shfl_xor_sync(0xffffffffu, v, o);
    return v;
}
__device__ __forceinline__ void ldsm4(uint32_t addr, uint32_t& r0, uint32_t& r1,
                                      uint32_t& r2, uint32_t& r3) {
    asm volatile("ldmatrix.sync.aligned.m8n8.x4.shared.b16 {%0,%1,%2,%3}, [%4];"
                 : "=r"(r0), "=r"(r1), "=r"(r2), "=r"(r3) : "r"(addr));
}
__device__ __forceinline__ void mma16816(float d[4], const uint32_t a[4],
                                         uint32_t b0, uint32_t b1) {
    asm volatile("mma.sync.aligned.m16n8k16.row.col.f32.f16.f16.f32 "
                 "{%0,%1,%2,%3}, {%4,%5,%6,%7}, {%8,%9}, {%0,%1,%2,%3};"
                 : "+f"(d[0]), "+f"(d[1]), "+f"(d[2]), "+f"(d[3])
                 : "r"(a[0]), "r"(a[1]), "r"(a[2]), "r"(a[3]), "r"(b0), "r"(b1));
}
__device__ __forceinline__ void load_img1(const unsigned char* g, unsigned char* s, int t) {
    const uint4* src = (const uint4*)g;
    uint4* dst = (uint4*)s;
    for (int i = t; i < 2048; i += 512) {
        int r = i >> 4, c = i & 15;
        dst[r * 17 + c] = src[i];
    }
}
__device__ __forceinline__ void store_img1(unsigned char* g, const unsigned char* s, int t) {
    uint4* dst = (uint4*)g;
    const uint4* src = (const uint4*)s;
    for (int i = t; i < 2048; i += 512) {
        int r = i >> 4, c = i & 15;
        dst[i] = src[r * 17 + c];
    }
}
// async image load: gmem packed -> smem padded, 16B chunks via cp.async
__device__ __forceinline__ void load_img1_async(const unsigned char* g, uint32_t s, int t) {
    for (int i = t; i < 2048; i += 512) {
        int r = i >> 4, c = i & 15;
        asm volatile("cp.async.cg.shared.global [%0], [%1], 16;"
                     :: "r"(s + (uint32_t)((r * 17 + c) * 16)), "l"(g + (size_t)i * 16)
                     : "memory");
    }
}
#define CP_COMMIT() asm volatile("cp.async.commit_group;" ::: "memory")
#define CP_WAIT(n)  asm volatile("cp.async.wait_group %0;" :: "n"(n) : "memory")

// single-pass fp16 GEMM: D(32x32) += A * B^T ; 16 warps, 4x4 warp grid.
__device__ __forceinline__ void gemm1f(uint32_t A, uint32_t B, int wm, int wn,
                                       int lane, float D[2][4][4]) {
    int mat = lane >> 3, r8 = lane & 7;
    int arow = wm * 32 + ((mat & 1) << 3) + r8;
    int acol0 = (mat >> 1) << 3;
    int brow = wn * 32 + ((mat >> 1) << 3) + r8;
    int bcol0 = (mat & 1) << 3;
    #pragma unroll
    for (int ks = 0; ks < 8; ks++) {
        int k = ks * 16;
        uint32_t a[2][4], bf[2][4];
        #pragma unroll
        for (int mt = 0; mt < 2; mt++)
            ldsm4(A + (arow + mt * 16) * ROWB + (k + acol0) * 2,
                  a[mt][0], a[mt][1], a[mt][2], a[mt][3]);
        #pragma unroll
        for (int bt = 0; bt < 2; bt++)
            ldsm4(B + (brow + bt * 16) * ROWB + (k + bcol0) * 2,
                  bf[bt][0], bf[bt][1], bf[bt][2], bf[bt][3]);
        #pragma unroll
        for (int mt = 0; mt < 2; mt++)
            #pragma unroll
            for (int nt = 0; nt < 4; nt++)
                mma16816(D[mt][nt], a[mt], bf[nt >> 1][(nt & 1) * 2],
                         bf[nt >> 1][(nt & 1) * 2 + 1]);
    }
}
__device__ __forceinline__ void dzero(float D[2][4][4]) {
    #pragma unroll
    for (int mt = 0; mt < 2; mt++)
        #pragma unroll
        for (int nt = 0; nt < 4; nt++)
            #pragma unroll
            for (int i = 0; i < 4; i++) D[mt][nt][i] = 0.0f;
}
__device__ __forceinline__ void dwrite(float* Dsm, int wm, int wn, int lane, float D[2][4][4]) {
    int r = lane >> 2, cc = (lane & 3) * 2;
    #pragma unroll
    for (int mt = 0; mt < 2; mt++)
        #pragma unroll
        for (int nt = 0; nt < 4; nt++) {
            int row = wm * 32 + mt * 16 + r;
            int col = wn * 32 + nt * 8 + cc;
            Dsm[row * 129 + col] = D[mt][nt][0];
            Dsm[row * 129 + col + 1] = D[mt][nt][1];
            Dsm[(row + 8) * 129 + col] = D[mt][nt][2];
            Dsm[(row + 8) * 129 + col + 1] = D[mt][nt][3];
        }
}

// ---------------- P: merged prolog (keysm | zero_kv | prepw | biasdyn) ----
__global__ __launch_bounds__(256) void k_prolog(const float* __restrict__ mem,
                                                const float* __restrict__ nv1,
                                                const float* __restrict__ nv2,
                                                const float* __restrict__ bpool,
                                                const float* __restrict__ qw,
                                                const float* __restrict__ vw,
                                                const float* __restrict__ cw,
                                                const float* __restrict__ wpool) {
    extern __shared__ __align__(16) unsigned char psm[];
    int p = blockIdx.x;
    int t = threadIdx.x;
    const float inv_scale = 0.17677669529663687f;

    if (p < 1024) {                      // ---- keysm ----
        int row = p * 8 + (t >> 5);
        int lane = t & 31;
        float v = mem[row * 32 + lane] * inv_scale;
        float m = warp_max(v);
        float e = __expf(v - m);
        float s = warp_sum(e);
        g_keysm[row * 32 + lane] = e / s;
        return;
    }
    if (p < 1088) {                      // ---- zero_kv ----
        float4* kv4 = (float4*)g_kv;
        int base = (p - 1024) * 1024;
        #pragma unroll
        for (int i = 0; i < 4; i++)
            kv4[base + t + i * 256] = make_float4(0.f, 0.f, 0.f, 0.f);
        return;
    }
    if (p < 1120) {                      // ---- prepw ----
        if (t >= 128) return;
        int pb = p - 1088;
        int m = pb >> 3, part = pb & 7;
        int o = t;
        if (m == 3) {
            if (part == 0) {
                for (int y = 0; y < 32; y++) {
                    float s = 0.0f;
                    #pragma unroll
                    for (int h = 0; h < 4; h++) s += cw[o * 128 + h * 32 + y];
                    g_Cp[o * 32 + y] = s;
                }
            }
            return;
        }
        const float* w = (m == 0) ? qw : (m == 1) ? vw : cw;
        float scale = 1.0f;
        if (m == 2) {
            float S = 0.0f;
            #pragma unroll
            for (int i = 0; i < 9; i++) S += wpool[i];
            scale = S;
        }
        unsigned char* img = g_wimg + m * 32768;
        for (int cc = part * 2; cc < part * 2 + 2; cc++) {
            unsigned short hs[8];
            #pragma unroll
            for (int k = 0; k < 8; k++) hs[k] = hf1(w[o * 128 + cc * 8 + k] * scale);
            *(uint4*)(img + (o * 128 + cc * 8) * 2) = pack8(hs);
        }
        return;
    }
    // ---- biasdyn ----
    {
        float* pp = (float*)(psm + PL_P);
        float* red = (float*)(psm + PL_RED);
        float* a1 = (float*)(psm + PL_A1);
        float* invs = (float*)(psm + PL_INV);
        int n0 = (p - 1120) * 8;
        if (t < 80) a1[t] = nv1[(n0 + t / 10) * 10 + (t % 10)];
        __syncthreads();
        for (int r = 0; r < 8; r++) {
            float lv[8];
            float lmax = 0.0f;
            #pragma unroll
            for (int i = 0; i < 8; i++) {
                int m = t + i * 256;
                float acc = 0.0f;
                #pragma unroll
                for (int k = 0; k < 10; k++) acc += a1[r * 10 + k] * nv2[k * NN + m];
                acc = fmaxf(acc, 0.0f);
                lv[i] = acc;
                lmax = fmaxf(lmax, acc);
            }
            red[t] = lmax; __syncthreads();
            for (int s = 128; s; s >>= 1) { if (t < s) red[t] = fmaxf(red[t], red[t + s]); __syncthreads(); }
            float bmax = red[0];
            __syncthreads();
            float lsum = 0.0f;
            #pragma unroll
            for (int i = 0; i < 8; i++) {
                float e = __expf(lv[i] - bmax);
                pp[r * NN + t + i * 256] = e;
                lsum += e;
            }
            red[t] = lsum; __syncthreads();
            for (int s = 128; s; s >>= 1) { if (t < s) red[t] += red[t + s]; __syncthreads(); }
            if (t == 0) invs[r] = 1.0f / red[0];
            __syncthreads();
        }
        int c = t & 31, g = t >> 5;
        float acc[8];
        #pragma unroll
        for (int r = 0; r < 8; r++) acc[r] = 0.0f;
        for (int m = g; m < NN; m += 8) {
            float bp = bpool[m * 32 + c];
            #pragma unroll
            for (int r = 0; r < 8; r++) acc[r] += pp[r * NN + m] * bp;
        }
        for (int r = 0; r < 8; r++) {
            red[t] = acc[r]; __syncthreads();
            if (t < 32) {
                float s2 = 0.0f;
                #pragma unroll
                for (int g2 = 0; g2 < 8; g2++) s2 += red[g2 * 32 + t];
                g_biasdyn[(n0 + r) * 32 + t] = s2 * invs[r];
            }
            __syncthreads();
        }
    }
}

// ---------------- P4b: bias2 = Cp @ bias_dyn^T ----------------
__global__ __launch_bounds__(128) void k_bias2() {
    __shared__ float bd[32];
    int n = blockIdx.x, t = threadIdx.x;
    if (t < 32) bd[t] = g_biasdyn[n * 32 + t];
    __syncthreads();
    float s = 0.0f;
    #pragma unroll
    for (int y = 0; y < 32; y++) s += g_Cp[t * 32 + y] * bd[y];
    g_bias2[t * NN + n] = s;
}

// ---------------- K1: x convert + Q/V convs + softmax + kv partial --------
__global__ __launch_bounds__(512, 1) void k_qv(const float* __restrict__ x,
                                               const float* __restrict__ qb,
                                               const float* __restrict__ vb) {
    extern __shared__ __align__(16) unsigned char sm[];
    int b = blockIdx.y, tile = blockIdx.x, n0 = tile * NT, t = threadIdx.x;
    uint32_t sb = smem_u32(sm);
    float* Dsm = (float*)(sm + QV_D);
    float* sbias = (float*)(sm + QV_SB);
    int w = t >> 5, lane = t & 31;
    int wm = w >> 2, wn = w & 3;

    load_img1(g_wimg, sm + QV_A, t);                 // Wq
    for (int i = t; i < 16384; i += 512) {
        int c = i >> 7, n = i & 127;
        Dsm[c * 129 + n] = x[((size_t)b * 128 + c) * NN + n0 + n];
    }
    if (t < 128) sbias[t] = qb[t];
    else if (t < 256) sbias[t] = vb[t - 128];
    __syncthreads();

    {
        int node = t >> 2, q4 = t & 3;
        #pragma unroll
        for (int cc = 0; cc < 4; cc++) {
            int c0 = q4 * 32 + cc * 8;
            unsigned short hs[8];
            #pragma unroll
            for (int k = 0; k < 8; k++) hs[k] = hf1(Dsm[(c0 + k) * 129 + node]);
            *(uint4*)(sm + QV_B + node * ROWB + c0 * 2) = pack8(hs);
        }
    }
    __syncthreads();

    float D[2][4][4];
    dzero(D);
    gemm1f(sb + QV_A, sb + QV_B, wm, wn, lane, D);   // Q = Wq @ x
    dwrite(Dsm, wm, wn, lane, D);
    __syncthreads();

    const float inv_scale = 0.17677669529663687f;
    {
        int node = t & 127, h = t >> 7;
        float q[32];
        float mx = 0.0f;
        #pragma unroll
        for (int i = 0; i < 32; i++) {
            q[i] = fmaxf(Dsm[(h * 32 + i) * 129 + node] + sbias[h * 32 + i], 0.0f);
            mx = fmaxf(mx, q[i]);
        }
        float s = 0.0f;
        #pragma unroll
        for (int i = 0; i < 32; i++) { q[i] = __expf((q[i] - mx) * inv_scale); s += q[i]; }
        float is = 1.0f / s;
        #pragma unroll
        for (int cc = 0; cc < 4; cc++) {
            unsigned short hs[8];
            #pragma unroll
            for (int k = 0; k < 8; k++) hs[k] = hf1(q[cc * 8 + k] * is);
            *(uint4*)(sm + QV_Q + node * ROWB + (h * 32 + cc * 8) * 2) = pack8(hs);
        }
    }
    load_img1(g_wimg + 32768, sm + QV_A, t);         // Wv
    __syncthreads();

    store_img1(g_qimg + ((size_t)(b * NTILES + tile)) * 32768, sm + QV_Q, t);
    dzero(D);
    gemm1f(sb + QV_A, sb + QV_B, wm, wn, lane, D);   // V = Wv @ x
    dwrite(Dsm, wm, wn, lane, D);
    __syncthreads();

    {
        int node = t & 127, h = t >> 7;
        float v[32];
        #pragma unroll
        for (int i = 0; i < 32; i++) {
            v[i] = fmaxf(Dsm[(h * 32 + i) * 129 + node] + sbias[128 + h * 32 + i], 0.0f);
            Dsm[(h * 32 + i) * 129 + node] = v[i];
        }
        #pragma unroll
        for (int cc = 0; cc < 4; cc++) {
            unsigned short hs[8];
            #pragma unroll
            for (int k = 0; k < 8; k++) hs[k] = hf1(v[cc * 8 + k]);
            *(uint4*)(sm + QV_Q + node * ROWB + (h * 32 + cc * 8) * 2) = pack8(hs);
        }
    }
    float* ks = (float*)sm;   // spans A+B
    for (int i = t; i < 16384; i += 512) {
        int h2 = i >> 12, r = i & 4095;
        int j2 = r >> 5, xk = r & 31;
        ks[i] = g_keysm[(h2 * NN + n0 + j2) * 32 + xk];
    }
    __syncthreads();

    store_img1(g_vimg + ((size_t)(b * NTILES + tile)) * 32768, sm + QV_Q, t);
    {
        int idx = t & 127, h2 = t >> 7;
        int x0 = (idx >> 4) * 4, y0 = (idx & 15) * 2;
        float acc[4][2];
        #pragma unroll
        for (int a = 0; a < 4; a++) { acc[a][0] = 0.0f; acc[a][1] = 0.0f; }
        #pragma unroll 4
        for (int jj = 0; jj < NT; jj++) {
            float4 kx = *(const float4*)(ks + (h2 * NT + jj) * 32 + x0);
            float v0 = Dsm[(h2 * 32 + y0 + 0) * 129 + jj];
            float v1 = Dsm[(h2 * 32 + y0 + 1) * 129 + jj];
            acc[0][0] += kx.x * v0; acc[0][1] += kx.x * v1;
            acc[1][0] += kx.y * v0; acc[1][1] += kx.y * v1;
            acc[2][0] += kx.z * v0; acc[2][1] += kx.z * v1;
            acc[3][0] += kx.w * v0; acc[3][1] += kx.w * v1;
        }
        #pragma unroll
        for (int xi = 0; xi < 4; xi++)
            #pragma unroll
            for (int yi = 0; yi < 2; yi++)
                atomicAdd(&g_kv[(((size_t)b * HEAD + h2) * DK + x0 + xi) * DK + y0 + yi],
                          acc[xi][yi]);
    }
}

// ---------------- P6: Mb, head-partitioned: grid (64,4), 256 threads ------
__global__ __launch_bounds__(256) void k_mb(const float* __restrict__ cw) {
    __shared__ float kvs[32 * 33];
    int b = blockIdx.x, h = blockIdx.y, t = threadIdx.x;
    for (int i = t; i < 1024; i += 256) {
        int x = i >> 5, y = i & 31;
        kvs[x * 33 + y] = g_kv[((size_t)b * HEAD + h) * 1024 + i];
    }
    __syncthreads();
    int o = t >> 1, xh = t & 1;
    const float* cwrow = cw + o * 128 + h * 32;
    float acc[16];
    #pragma unroll
    for (int i = 0; i < 16; i++) acc[i] = 0.0f;
    for (int y = 0; y < 32; y++) {
        float cv = __ldg(cwrow + y);
        #pragma unroll
        for (int x8 = 0; x8 < 16; x8++)
            acc[x8] += cv * kvs[(xh * 16 + x8) * 33 + y];
    }
    unsigned char* img = g_Mb + (size_t)b * 32768;
    #pragma unroll
    for (int cc = 0; cc < 2; cc++) {
        unsigned short hs[8];
        #pragma unroll
        for (int k = 0; k < 8; k++) hs[k] = hf1(acc[cc * 8 + k]);
        *(uint4*)(img + (o * 128 + h * 32 + xh * 16 + cc * 8) * 2) = pack8(hs);
    }
}

// ---------------- K2: 2 tiles/CTA, cp.async pipelined --------------------
__global__ __launch_bounds__(512, 1) void k_out(const float* __restrict__ cb,
                                                const float* __restrict__ affw,
                                                const float* __restrict__ affb,
                                                float* __restrict__ out) {
    extern __shared__ __align__(16) unsigned char sm[];
    int b = blockIdx.y, pair = blockIdx.x, t = threadIdx.x;
    uint32_t sb = smem_u32(sm);
    int w = t >> 5, lane = t & 31;
    int wm = w >> 2, wn = w & 3;
    int tile0 = pair * 2;

    // group A: Mb, Cs, q0, v0
    load_img1_async(g_Mb + (size_t)b * 32768, sb + KO_A, t);
    load_img1_async(g_wimg + 2 * 32768, sb + KO_C, t);
    load_img1_async(g_qimg + ((size_t)(b * NTILES + tile0)) * 32768, sb + KO_BQ0, t);
    load_img1_async(g_vimg + ((size_t)(b * NTILES + tile0)) * 32768, sb + KO_BV0, t);
    CP_COMMIT();
    // group B: q1, v1 (streams under tile-0 compute)
    load_img1_async(g_qimg + ((size_t)(b * NTILES + tile0 + 1)) * 32768, sb + KO_BQ1, t);
    load_img1_async(g_vimg + ((size_t)(b * NTILES + tile0 + 1)) * 32768, sb + KO_BV1, t);
    CP_COMMIT();

    CP_WAIT(1);          // group A complete
    __syncthreads();

    int r0 = lane >> 2, cp = (lane & 3) * 2;
    #pragma unroll 1
    for (int tt = 0; tt < 2; tt++) {
        if (tt == 1) {
            CP_WAIT(0);  // group B complete
            __syncthreads();
        }
        int n0 = (tile0 + tt) * NT;
        float D[2][4][4];
        dzero(D);
        gemm1f(sb + KO_A, sb + (tt ? KO_BQ1 : KO_BQ0), wm, wn, lane, D);
        gemm1f(sb + KO_C, sb + (tt ? KO_BV1 : KO_BV0), wm, wn, lane, D);
        #pragma unroll
        for (int mt = 0; mt < 2; mt++)
            #pragma unroll
            for (int nt = 0; nt < 4; nt++) {
                int col = wn * 32 + nt * 8 + cp;
                #pragma unroll
                for (int half = 0; half < 2; half++) {
                    int c = wm * 32 + mt * 16 + r0 + half * 8;
                    size_t base = (size_t)c * NN + n0 + col;
                    float cbv = __ldg(cb + c);
                    float2 b2 = *(const float2*)(g_bias2 + base);
                    float2 aw = *(const float2*)(affw + base);
                    float2 ab = *(const float2*)(affb + base);
                    float v0 = D[mt][nt][half * 2 + 0] + cbv + b2.x;
                    float v1 = D[mt][nt][half * 2 + 1] + cbv + b2.y;
                    float rr0 = fmaxf(v0, 0.0f), rr1 = fmaxf(v1, 0.0f);
                    float2 o2;
                    o2.x = rr0 + rr0 * aw.x + ab.x;
                    o2.y = rr1 + rr1 * aw.y + ab.y;
                    *(float2*)(out + ((size_t)b * 128) * NN + base) = o2;
                }
            }
    }
}

extern "C" void kernel_launch(void* const* d_in, const int* in_sizes, int n_in,
                              void* d_out, int out_size) {
    const float* x     = (const float*)d_in[0];
    const float* qw    = (const float*)d_in[1];
    const float* qb    = (const float*)d_in[2];
    const float* vw    = (const float*)d_in[3];
    const float* vb    = (const float*)d_in[4];
    const float* cw    = (const float*)d_in[5];
    const float* cb    = (const float*)d_in[6];
    const float* mem   = (const float*)d_in[7];
    const float* nv1   = (const float*)d_in[8];
    const float* nv2   = (const float*)d_in[9];
    const float* wpool = (const float*)d_in[10];
    const float* bpool = (const float*)d_in[11];
    const float* affw  = (const float*)d_in[12];
    const float* affb  = (const float*)d_in[13];
    float* out = (float*)d_out;

    cudaFuncSetAttribute(k_prolog, cudaFuncAttributeMaxDynamicSharedMemorySize, SMEM_PL);
    k_prolog<<<1376, 256, SMEM_PL>>>(mem, nv1, nv2, bpool, qw, vw, cw, wpool);

    k_bias2<<<NN, 128>>>();

    cudaFuncSetAttribute(k_qv, cudaFuncAttributeMaxDynamicSharedMemorySize, SMEM_QV);
    k_qv<<<dim3(NTILES, BATCH), 512, SMEM_QV>>>(x, qb, vb);

    k_mb<<<dim3(BATCH, HEAD), 256>>>(cw);

    cudaFuncSetAttribute(k_out, cudaFuncAttributeMaxDynamicSharedMemorySize, SMEM_OUT);
    k_out<<<dim3(NTILES / 2, BATCH), 512, SMEM_OUT>>>(cb, affw, affb, out);
}

// round 17
// speedup vs baseline: 1.4341x; 1.4341x over previous
#include <cuda_runtime.h>
#include <cuda_fp16.h>
#include <math.h>
#include <stdint.h>

#define BATCH 64
#define DMODEL 128
#define NN 2048
#define HEAD 4
#define DK 32
#define NT 128
#define NTILES (NN/NT)  // 16

#define IMG_SZ 34816       // 128 rows * 272 B
#define ROWB 272
// k_qv: A | B | D fp32 | biases | Q(img staging)
#define QV_A 0
#define QV_B 34816
#define QV_D 69632         // fp32 [128][129]
#define QV_SB 135680
#define QV_Q 136704
#define SMEM_QV 171520
// k_out (2 tiles): Mb | Cs | q0 | v0 | q1 | v1
#define KO_A 0
#define KO_C 34816
#define KO_BQ0 69632
#define KO_BV0 104448
#define KO_BQ1 139264
#define KO_BV1 174080
#define SMEM_OUT 208896
// k_prolog dyn smem (biasdyn partition)
#define PL_P 0             // 65536 : p[8][2048]
#define PL_RED 65536       // 1024
#define PL_A1 66560        // 320
#define PL_INV 66880       // 32
#define SMEM_PL 66944

// ---------------- device globals ----------------
static __device__ float g_keysm[HEAD * NN * DK];
static __device__ float g_biasdyn[NN * DK];
static __device__ float g_kv[BATCH * HEAD * DK * DK];
static __device__ float g_bias2[DMODEL * NN];
static __device__ float g_Cp[DMODEL * DK];
static __device__ __align__(16) unsigned char g_wimg[3 * 32768];                      // Wq, Wv, Cs
static __device__ __align__(16) unsigned char g_qimg[(size_t)BATCH * NTILES * 32768];
static __device__ __align__(16) unsigned char g_vimg[(size_t)BATCH * NTILES * 32768];
static __device__ __align__(16) unsigned char g_Mb[(size_t)BATCH * 32768];

// ---------------- helpers ----------------
__device__ __forceinline__ uint32_t smem_u32(const void* p) {
    uint32_t a;
    asm("{ .reg .u64 t; cvta.to.shared.u64 t, %1; cvt.u32.u64 %0, t; }" : "=r"(a) : "l"(p));
    return a;
}
__device__ __forceinline__ unsigned short hf1(float v) {
    return __half_as_ushort(__float2half_rn(v));
}
__device__ __forceinline__ uint4 pack8(const unsigned short* h) {
    uint4 u;
    u.x = (uint32_t)h[0] | ((uint32_t)h[1] << 16);
    u.y = (uint32_t)h[2] | ((uint32_t)h[3] << 16);
    u.z = (uint32_t)h[4] | ((uint32_t)h[5] << 16);
    u.w = (uint32_t)h[6] | ((uint32_t)h[7] << 16);
    return u;
}
__device__ __forceinline__ float warp_max(float v) {
    #pragma unroll
    for (int o = 16; o; o >>= 1) v = fmaxf(v, __shfl_xor_sync(0xffffffffu, v, o));
    return v;
}
__device__ __forceinline__ float warp_sum(float v) {
    #pragma unroll
    for (int o = 16; o; o >>= 1) v += __shfl_xor_sync(0xffffffffu, v, o);
    return v;
}
__device__ __forceinline__ void ldsm4(uint32_t addr, uint32_t& r0, uint32_t& r1,
                                      uint32_t& r2, uint32_t& r3) {
    asm volatile("ldmatrix.sync.aligned.m8n8.x4.shared.b16 {%0,%1,%2,%3}, [%4];"
                 : "=r"(r0), "=r"(r1), "=r"(r2), "=r"(r3) : "r"(addr));
}
__device__ __forceinline__ void mma16816(float d[4], const uint32_t a[4],
                                         uint32_t b0, uint32_t b1) {
    asm volatile("mma.sync.aligned.m16n8k16.row.col.f32.f16.f16.f32 "
                 "{%0,%1,%2,%3}, {%4,%5,%6,%7}, {%8,%9}, {%0,%1,%2,%3};"
                 : "+f"(d[0]), "+f"(d[1]), "+f"(d[2]), "+f"(d[3])
                 : "r"(a[0]), "r"(a[1]), "r"(a[2]), "r"(a[3]), "r"(b0), "r"(b1));
}
__device__ __forceinline__ void load_img1(const unsigned char* g, unsigned char* s, int t) {
    const uint4* src = (const uint4*)g;
    uint4* dst = (uint4*)s;
    for (int i = t; i < 2048; i += 512) {
        int r = i >> 4, c = i & 15;
        dst[r * 17 + c] = src[i];
    }
}
__device__ __forceinline__ void store_img1(unsigned char* g, const unsigned char* s, int t) {
    uint4* dst = (uint4*)g;
    const uint4* src = (const uint4*)s;
    for (int i = t; i < 2048; i += 512) {
        int r = i >> 4, c = i & 15;
        dst[i] = src[r * 17 + c];
    }
}
__device__ __forceinline__ void stcs2(float* p, float2 v) {
    asm volatile("st.global.cs.v2.f32 [%0], {%1, %2};" :: "l"(p), "f"(v.x), "f"(v.y) : "memory");
}

// single-pass fp16 GEMM: D(32x32) += A * B^T ; 16 warps, 4x4 warp grid.
__device__ __forceinline__ void gemm1f(uint32_t A, uint32_t B, int wm, int wn,
                                       int lane, float D[2][4][4]) {
    int mat = lane >> 3, r8 = lane & 7;
    int arow = wm * 32 + ((mat & 1) << 3) + r8;
    int acol0 = (mat >> 1) << 3;
    int brow = wn * 32 + ((mat >> 1) << 3) + r8;
    int bcol0 = (mat & 1) << 3;
    #pragma unroll
    for (int ks = 0; ks < 8; ks++) {
        int k = ks * 16;
        uint32_t a[2][4], bf[2][4];
        #pragma unroll
        for (int mt = 0; mt < 2; mt++)
            ldsm4(A + (arow + mt * 16) * ROWB + (k + acol0) * 2,
                  a[mt][0], a[mt][1], a[mt][2], a[mt][3]);
        #pragma unroll
        for (int bt = 0; bt < 2; bt++)
            ldsm4(B + (brow + bt * 16) * ROWB + (k + bcol0) * 2,
                  bf[bt][0], bf[bt][1], bf[bt][2], bf[bt][3]);
        #pragma unroll
        for (int mt = 0; mt < 2; mt++)
            #pragma unroll
            for (int nt = 0; nt < 4; nt++)
                mma16816(D[mt][nt], a[mt], bf[nt >> 1][(nt & 1) * 2],
                         bf[nt >> 1][(nt & 1) * 2 + 1]);
    }
}
__device__ __forceinline__ void dzero(float D[2][4][4]) {
    #pragma unroll
    for (int mt = 0; mt < 2; mt++)
        #pragma unroll
        for (int nt = 0; nt < 4; nt++)
            #pragma unroll
            for (int i = 0; i < 4; i++) D[mt][nt][i] = 0.0f;
}
__device__ __forceinline__ void dwrite(float* Dsm, int wm, int wn, int lane, float D[2][4][4]) {
    int r = lane >> 2, cc = (lane & 3) * 2;
    #pragma unroll
    for (int mt = 0; mt < 2; mt++)
        #pragma unroll
        for (int nt = 0; nt < 4; nt++) {
            int row = wm * 32 + mt * 16 + r;
            int col = wn * 32 + nt * 8 + cc;
            Dsm[row * 129 + col] = D[mt][nt][0];
            Dsm[row * 129 + col + 1] = D[mt][nt][1];
            Dsm[(row + 8) * 129 + col] = D[mt][nt][2];
            Dsm[(row + 8) * 129 + col + 1] = D[mt][nt][3];
        }
}

// ---------------- P: merged prolog (keysm | zero_kv | prepw | biasdyn) ----
__global__ __launch_bounds__(256) void k_prolog(const float* __restrict__ mem,
                                                const float* __restrict__ nv1,
                                                const float* __restrict__ nv2,
                                                const float* __restrict__ bpool,
                                                const float* __restrict__ qw,
                                                const float* __restrict__ vw,
                                                const float* __restrict__ cw,
                                                const float* __restrict__ wpool) {
    extern __shared__ __align__(16) unsigned char psm[];
    int p = blockIdx.x;
    int t = threadIdx.x;
    const float inv_scale = 0.17677669529663687f;

    if (p < 1024) {                      // ---- keysm ----
        int row = p * 8 + (t >> 5);
        int lane = t & 31;
        float v = mem[row * 32 + lane] * inv_scale;
        float m = warp_max(v);
        float e = __expf(v - m);
        float s = warp_sum(e);
        g_keysm[row * 32 + lane] = e / s;
        return;
    }
    if (p < 1088) {                      // ---- zero_kv ----
        float4* kv4 = (float4*)g_kv;
        int base = (p - 1024) * 1024;
        #pragma unroll
        for (int i = 0; i < 4; i++)
            kv4[base + t + i * 256] = make_float4(0.f, 0.f, 0.f, 0.f);
        return;
    }
    if (p < 1120) {                      // ---- prepw ----
        if (t >= 128) return;
        int pb = p - 1088;
        int m = pb >> 3, part = pb & 7;
        int o = t;
        if (m == 3) {
            if (part == 0) {
                for (int y = 0; y < 32; y++) {
                    float s = 0.0f;
                    #pragma unroll
                    for (int h = 0; h < 4; h++) s += cw[o * 128 + h * 32 + y];
                    g_Cp[o * 32 + y] = s;
                }
            }
            return;
        }
        const float* w = (m == 0) ? qw : (m == 1) ? vw : cw;
        float scale = 1.0f;
        if (m == 2) {
            float S = 0.0f;
            #pragma unroll
            for (int i = 0; i < 9; i++) S += wpool[i];
            scale = S;
        }
        unsigned char* img = g_wimg + m * 32768;
        for (int cc = part * 2; cc < part * 2 + 2; cc++) {
            unsigned short hs[8];
            #pragma unroll
            for (int k = 0; k < 8; k++) hs[k] = hf1(w[o * 128 + cc * 8 + k] * scale);
            *(uint4*)(img + (o * 128 + cc * 8) * 2) = pack8(hs);
        }
        return;
    }
    // ---- biasdyn ----
    {
        float* pp = (float*)(psm + PL_P);
        float* red = (float*)(psm + PL_RED);
        float* a1 = (float*)(psm + PL_A1);
        float* invs = (float*)(psm + PL_INV);
        int n0 = (p - 1120) * 8;
        if (t < 80) a1[t] = nv1[(n0 + t / 10) * 10 + (t % 10)];
        __syncthreads();
        for (int r = 0; r < 8; r++) {
            float lv[8];
            float lmax = 0.0f;
            #pragma unroll
            for (int i = 0; i < 8; i++) {
                int m = t + i * 256;
                float acc = 0.0f;
                #pragma unroll
                for (int k = 0; k < 10; k++) acc += a1[r * 10 + k] * nv2[k * NN + m];
                acc = fmaxf(acc, 0.0f);
                lv[i] = acc;
                lmax = fmaxf(lmax, acc);
            }
            red[t] = lmax; __syncthreads();
            for (int s = 128; s; s >>= 1) { if (t < s) red[t] = fmaxf(red[t], red[t + s]); __syncthreads(); }
            float bmax = red[0];
            __syncthreads();
            float lsum = 0.0f;
            #pragma unroll
            for (int i = 0; i < 8; i++) {
                float e = __expf(lv[i] - bmax);
                pp[r * NN + t + i * 256] = e;
                lsum += e;
            }
            red[t] = lsum; __syncthreads();
            for (int s = 128; s; s >>= 1) { if (t < s) red[t] += red[t + s]; __syncthreads(); }
            if (t == 0) invs[r] = 1.0f / red[0];
            __syncthreads();
        }
        int c = t & 31, g = t >> 5;
        float acc[8];
        #pragma unroll
        for (int r = 0; r < 8; r++) acc[r] = 0.0f;
        for (int m = g; m < NN; m += 8) {
            float bp = bpool[m * 32 + c];
            #pragma unroll
            for (int r = 0; r < 8; r++) acc[r] += pp[r * NN + m] * bp;
        }
        for (int r = 0; r < 8; r++) {
            red[t] = acc[r]; __syncthreads();
            if (t < 32) {
                float s2 = 0.0f;
                #pragma unroll
                for (int g2 = 0; g2 < 8; g2++) s2 += red[g2 * 32 + t];
                g_biasdyn[(n0 + r) * 32 + t] = s2 * invs[r];
            }
            __syncthreads();
        }
    }
}

// ---------------- P4b: bias2 = Cp @ bias_dyn^T ----------------
__global__ __launch_bounds__(128) void k_bias2() {
    __shared__ float bd[32];
    int n = blockIdx.x, t = threadIdx.x;
    if (t < 32) bd[t] = g_biasdyn[n * 32 + t];
    __syncthreads();
    float s = 0.0f;
    #pragma unroll
    for (int y = 0; y < 32; y++) s += g_Cp[t * 32 + y] * bd[y];
    g_bias2[t * NN + n] = s;
}

// ---------------- K1: x convert + Q/V convs + softmax + kv partial --------
__global__ __launch_bounds__(512, 1) void k_qv(const float* __restrict__ x,
                                               const float* __restrict__ qb,
                                               const float* __restrict__ vb) {
    extern __shared__ __align__(16) unsigned char sm[];
    int b = blockIdx.y, tile = blockIdx.x, n0 = tile * NT, t = threadIdx.x;
    uint32_t sb = smem_u32(sm);
    float* Dsm = (float*)(sm + QV_D);
    float* sbias = (float*)(sm + QV_SB);
    int w = t >> 5, lane = t & 31;
    int wm = w >> 2, wn = w & 3;

    load_img1(g_wimg, sm + QV_A, t);                 // Wq
    for (int i = t; i < 16384; i += 512) {
        int c = i >> 7, n = i & 127;
        Dsm[c * 129 + n] = __ldcs(x + ((size_t)b * 128 + c) * NN + n0 + n);
    }
    if (t < 128) sbias[t] = qb[t];
    else if (t < 256) sbias[t] = vb[t - 128];
    __syncthreads();

    {
        int node = t >> 2, q4 = t & 3;
        #pragma unroll
        for (int cc = 0; cc < 4; cc++) {
            int c0 = q4 * 32 + cc * 8;
            unsigned short hs[8];
            #pragma unroll
            for (int k = 0; k < 8; k++) hs[k] = hf1(Dsm[(c0 + k) * 129 + node]);
            *(uint4*)(sm + QV_B + node * ROWB + c0 * 2) = pack8(hs);
        }
    }
    __syncthreads();

    float D[2][4][4];
    dzero(D);
    gemm1f(sb + QV_A, sb + QV_B, wm, wn, lane, D);   // Q = Wq @ x
    dwrite(Dsm, wm, wn, lane, D);
    __syncthreads();

    const float inv_scale = 0.17677669529663687f;
    {
        int node = t & 127, h = t >> 7;
        float q[32];
        float mx = 0.0f;
        #pragma unroll
        for (int i = 0; i < 32; i++) {
            q[i] = fmaxf(Dsm[(h * 32 + i) * 129 + node] + sbias[h * 32 + i], 0.0f);
            mx = fmaxf(mx, q[i]);
        }
        float s = 0.0f;
        #pragma unroll
        for (int i = 0; i < 32; i++) { q[i] = __expf((q[i] - mx) * inv_scale); s += q[i]; }
        float is = 1.0f / s;
        #pragma unroll
        for (int cc = 0; cc < 4; cc++) {
            unsigned short hs[8];
            #pragma unroll
            for (int k = 0; k < 8; k++) hs[k] = hf1(q[cc * 8 + k] * is);
            *(uint4*)(sm + QV_Q + node * ROWB + (h * 32 + cc * 8) * 2) = pack8(hs);
        }
    }
    load_img1(g_wimg + 32768, sm + QV_A, t);         // Wv
    __syncthreads();

    store_img1(g_qimg + ((size_t)(b * NTILES + tile)) * 32768, sm + QV_Q, t);
    dzero(D);
    gemm1f(sb + QV_A, sb + QV_B, wm, wn, lane, D);   // V = Wv @ x
    dwrite(Dsm, wm, wn, lane, D);
    __syncthreads();

    {
        int node = t & 127, h = t >> 7;
        float v[32];
        #pragma unroll
        for (int i = 0; i < 32; i++) {
            v[i] = fmaxf(Dsm[(h * 32 + i) * 129 + node] + sbias[128 + h * 32 + i], 0.0f);
            Dsm[(h * 32 + i) * 129 + node] = v[i];
        }
        #pragma unroll
        for (int cc = 0; cc < 4; cc++) {
            unsigned short hs[8];
            #pragma unroll
            for (int k = 0; k < 8; k++) hs[k] = hf1(v[cc * 8 + k]);
            *(uint4*)(sm + QV_Q + node * ROWB + (h * 32 + cc * 8) * 2) = pack8(hs);
        }
    }
    float* ks = (float*)sm;   // spans A+B
    for (int i = t; i < 16384; i += 512) {
        int h2 = i >> 12, r = i & 4095;
        int j2 = r >> 5, xk = r & 31;
        ks[i] = g_keysm[(h2 * NN + n0 + j2) * 32 + xk];
    }
    __syncthreads();

    store_img1(g_vimg + ((size_t)(b * NTILES + tile)) * 32768, sm + QV_Q, t);
    {
        int idx = t & 127, h2 = t >> 7;
        int x0 = (idx >> 4) * 4, y0 = (idx & 15) * 2;
        float acc[4][2];
        #pragma unroll
        for (int a = 0; a < 4; a++) { acc[a][0] = 0.0f; acc[a][1] = 0.0f; }
        #pragma unroll 4
        for (int jj = 0; jj < NT; jj++) {
            float4 kx = *(const float4*)(ks + (h2 * NT + jj) * 32 + x0);
            float v0 = Dsm[(h2 * 32 + y0 + 0) * 129 + jj];
            float v1 = Dsm[(h2 * 32 + y0 + 1) * 129 + jj];
            acc[0][0] += kx.x * v0; acc[0][1] += kx.x * v1;
            acc[1][0] += kx.y * v0; acc[1][1] += kx.y * v1;
            acc[2][0] += kx.z * v0; acc[2][1] += kx.z * v1;
            acc[3][0] += kx.w * v0; acc[3][1] += kx.w * v1;
        }
        #pragma unroll
        for (int xi = 0; xi < 4; xi++)
            #pragma unroll
            for (int yi = 0; yi < 2; yi++)
                atomicAdd(&g_kv[(((size_t)b * HEAD + h2) * DK + x0 + xi) * DK + y0 + yi],
                          acc[xi][yi]);
    }
}

// ---------------- P6: Mb, head-partitioned: grid (64,4), 256 threads ------
__global__ __launch_bounds__(256) void k_mb(const float* __restrict__ cw) {
    __shared__ float kvs[32 * 33];
    int b = blockIdx.x, h = blockIdx.y, t = threadIdx.x;
    for (int i = t; i < 1024; i += 256) {
        int x = i >> 5, y = i & 31;
        kvs[x * 33 + y] = g_kv[((size_t)b * HEAD + h) * 1024 + i];
    }
    __syncthreads();
    int o = t >> 1, xh = t & 1;
    const float* cwrow = cw + o * 128 + h * 32;
    float acc[16];
    #pragma unroll
    for (int i = 0; i < 16; i++) acc[i] = 0.0f;
    for (int y = 0; y < 32; y++) {
        float cv = __ldg(cwrow + y);
        #pragma unroll
        for (int x8 = 0; x8 < 16; x8++)
            acc[x8] += cv * kvs[(xh * 16 + x8) * 33 + y];
    }
    unsigned char* img = g_Mb + (size_t)b * 32768;
    #pragma unroll
    for (int cc = 0; cc < 2; cc++) {
        unsigned short hs[8];
        #pragma unroll
        for (int k = 0; k < 8; k++) hs[k] = hf1(acc[cc * 8 + k]);
        *(uint4*)(img + (o * 128 + h * 32 + xh * 16 + cc * 8) * 2) = pack8(hs);
    }
}

// ---------------- K2: 2 tiles/CTA; out = relu(Mb@q + Cs@v + b2 + cb) -----
__global__ __launch_bounds__(512, 1) void k_out(const float* __restrict__ cb,
                                                const float* __restrict__ affw,
                                                const float* __restrict__ affb,
                                                float* __restrict__ out) {
    extern __shared__ __align__(16) unsigned char sm[];
    int b = blockIdx.y, pair = blockIdx.x, t = threadIdx.x;
    uint32_t sb = smem_u32(sm);
    int w = t >> 5, lane = t & 31;
    int wm = w >> 2, wn = w & 3;
    int tile0 = pair * 2;

    load_img1(g_Mb + (size_t)b * 32768, sm + KO_A, t);
    load_img1(g_wimg + 2 * 32768, sm + KO_C, t);
    load_img1(g_qimg + ((size_t)(b * NTILES + tile0)) * 32768, sm + KO_BQ0, t);
    load_img1(g_vimg + ((size_t)(b * NTILES + tile0)) * 32768, sm + KO_BV0, t);
    load_img1(g_qimg + ((size_t)(b * NTILES + tile0 + 1)) * 32768, sm + KO_BQ1, t);
    load_img1(g_vimg + ((size_t)(b * NTILES + tile0 + 1)) * 32768, sm + KO_BV1, t);
    __syncthreads();

    int r0 = lane >> 2, cp = (lane & 3) * 2;
    #pragma unroll 1
    for (int tt = 0; tt < 2; tt++) {
        int n0 = (tile0 + tt) * NT;
        float D[2][4][4];
        dzero(D);
        gemm1f(sb + KO_A, sb + (tt ? KO_BQ1 : KO_BQ0), wm, wn, lane, D);
        gemm1f(sb + KO_C, sb + (tt ? KO_BV1 : KO_BV0), wm, wn, lane, D);
        #pragma unroll
        for (int mt = 0; mt < 2; mt++)
            #pragma unroll
            for (int nt = 0; nt < 4; nt++) {
                int col = wn * 32 + nt * 8 + cp;
                #pragma unroll
                for (int half = 0; half < 2; half++) {
                    int c = wm * 32 + mt * 16 + r0 + half * 8;
                    size_t base = (size_t)c * NN + n0 + col;
                    float cbv = __ldg(cb + c);
                    float2 b2 = *(const float2*)(g_bias2 + base);
                    float2 aw = *(const float2*)(affw + base);
                    float2 ab = *(const float2*)(affb + base);
                    float v0 = D[mt][nt][half * 2 + 0] + cbv + b2.x;
                    float v1 = D[mt][nt][half * 2 + 1] + cbv + b2.y;
                    float rr0 = fmaxf(v0, 0.0f), rr1 = fmaxf(v1, 0.0f);
                    float2 o2;
                    o2.x = rr0 + rr0 * aw.x + ab.x;
                    o2.y = rr1 + rr1 * aw.y + ab.y;
                    stcs2(out + ((size_t)b * 128) * NN + base, o2);
                }
            }
    }
}

extern "C" void kernel_launch(void* const* d_in, const int* in_sizes, int n_in,
                              void* d_out, int out_size) {
    const float* x     = (const float*)d_in[0];
    const float* qw    = (const float*)d_in[1];
    const float* qb    = (const float*)d_in[2];
    const float* vw    = (const float*)d_in[3];
    const float* vb    = (const float*)d_in[4];
    const float* cw    = (const float*)d_in[5];
    const float* cb    = (const float*)d_in[6];
    const float* mem   = (const float*)d_in[7];
    const float* nv1   = (const float*)d_in[8];
    const float* nv2   = (const float*)d_in[9];
    const float* wpool = (const float*)d_in[10];
    const float* bpool = (const float*)d_in[11];
    const float* affw  = (const float*)d_in[12];
    const float* affb  = (const float*)d_in[13];
    float* out = (float*)d_out;

    cudaFuncSetAttribute(k_prolog, cudaFuncAttributeMaxDynamicSharedMemorySize, SMEM_PL);
    k_prolog<<<1376, 256, SMEM_PL>>>(mem, nv1, nv2, bpool, qw, vw, cw, wpool);

    k_bias2<<<NN, 128>>>();

    cudaFuncSetAttribute(k_qv, cudaFuncAttributeMaxDynamicSharedMemorySize, SMEM_QV);
    k_qv<<<dim3(NTILES, BATCH), 512, SMEM_QV>>>(x, qb, vb);

    k_mb<<<dim3(BATCH, HEAD), 256>>>(cw);

    cudaFuncSetAttribute(k_out, cudaFuncAttributeMaxDynamicSharedMemorySize, SMEM_OUT);
    k_out<<<dim3(NTILES / 2, BATCH), 512, SMEM_OUT>>>(cb, affw, affb, out);
}